// round 1
// baseline (speedup 1.0000x reference)
#include <cuda_runtime.h>
#include <cstdint>

#define NQ  900
#define BATCH 8
#define DIM 256
#define NH  8
#define DH  32
#define NLVL 4
#define NPT 4
#define DFF 1024
#define STOT 19947

#define MROWS (NQ*BATCH)          // 7200
#define VROWS (BATCH*STOT)        // 159576

// ---------------- scratch (device globals; no allocation allowed) ----------------
__device__ float g_q[MROWS*DIM];          // tgt+pos, (l*B+b, 256)
__device__ float g_qkv[MROWS*768];        // qh|kh|vh
__device__ float g_attn_o[MROWS*DIM];
__device__ float g_buf1[MROWS*DIM];
__device__ float g_tgt1[MROWS*DIM];
__device__ float g_query[MROWS*DIM];      // (b*NQ+l, 256)
__device__ float g_value[(size_t)VROWS*DIM]; // (b*S+s, 256)
__device__ float g_off[MROWS*DIM];        // (b*NQ+q, 256)
__device__ float g_aw[MROWS*128];
__device__ float g_ca[MROWS*DIM];         // sampled acc (b*NQ+q, 256)
__device__ float g_buf2[MROWS*DIM];
__device__ float g_tgt2[MROWS*DIM];
__device__ float g_h[MROWS*DFF];

// ---------------- generic SGEMM: C = A(MxK) * W(NxK)^T + bias, optional relu ----
// optional A-row permutation: arow = (r % permP1)*permP2 + r/permP1
__global__ void sgemm_kernel(const float* __restrict__ A, const float* __restrict__ W,
                             const float* __restrict__ bias, float* __restrict__ C,
                             int M, int N, int K, int ldC, int colOff,
                             int permP1, int permP2, int relu)
{
    __shared__ float As[8][128];
    __shared__ float Bs[8][128];
    int tid = threadIdx.x;
    int brow = blockIdx.y * 128;
    int bcol = blockIdx.x * 128;
    int tx = tid & 15;          // col group
    int ty = tid >> 4;          // row group
    float acc[8][8];
#pragma unroll
    for (int i = 0; i < 8; i++)
#pragma unroll
        for (int j = 0; j < 8; j++) acc[i][j] = 0.f;

    int lr  = tid >> 1;         // 0..127
    int lc4 = (tid & 1) * 4;    // 0 or 4

    for (int k0 = 0; k0 < K; k0 += 8) {
        // load A tile (128 x 8)
        float4 av = make_float4(0.f, 0.f, 0.f, 0.f);
        int r = brow + lr;
        if (r < M) {
            int ar = r;
            if (permP1 > 0) ar = (r % permP1) * permP2 + r / permP1;
            av = *(const float4*)(A + (size_t)ar * K + k0 + lc4);
        }
        As[lc4+0][lr] = av.x; As[lc4+1][lr] = av.y;
        As[lc4+2][lr] = av.z; As[lc4+3][lr] = av.w;
        // load W tile (128 x 8)
        float4 bv = make_float4(0.f, 0.f, 0.f, 0.f);
        int wr = bcol + lr;
        if (wr < N) bv = *(const float4*)(W + (size_t)wr * K + k0 + lc4);
        Bs[lc4+0][lr] = bv.x; Bs[lc4+1][lr] = bv.y;
        Bs[lc4+2][lr] = bv.z; Bs[lc4+3][lr] = bv.w;
        __syncthreads();
#pragma unroll
        for (int kk = 0; kk < 8; kk++) {
            float a[8], b[8];
#pragma unroll
            for (int i = 0; i < 8; i++) a[i] = As[kk][ty + i*16];
#pragma unroll
            for (int j = 0; j < 8; j++) b[j] = Bs[kk][tx + j*16];
#pragma unroll
            for (int i = 0; i < 8; i++)
#pragma unroll
                for (int j = 0; j < 8; j++) acc[i][j] += a[i] * b[j];
        }
        __syncthreads();
    }
#pragma unroll
    for (int i = 0; i < 8; i++) {
        int r = brow + ty + i*16;
        if (r >= M) continue;
#pragma unroll
        for (int j = 0; j < 8; j++) {
            int c = bcol + tx + j*16;
            if (c >= N) continue;
            float v = acc[i][j] + bias[c];
            if (relu) v = fmaxf(v, 0.f);
            C[(size_t)r * ldC + colOff + c] = v;
        }
    }
}

static void sgemm(const float* A, const float* W, const float* bias, float* C,
                  int M, int N, int K, int ldC, int colOff,
                  int permP1, int permP2, int relu)
{
    dim3 grid((N + 127) / 128, (M + 127) / 128);
    sgemm_kernel<<<grid, 256>>>(A, W, bias, C, M, N, K, ldC, colOff, permP1, permP2, relu);
}

// ---------------- elementwise builders ----------------
__global__ void build_q_kernel(const float* __restrict__ tgt, const float* __restrict__ pos,
                               float* __restrict__ out)
{
    int i = blockIdx.x * blockDim.x + threadIdx.x;
    if (i < MROWS * DIM) out[i] = tgt[i] + pos[i];
}

// query[b*NQ+l] = tgt1[l*B+b] + pos[l*B+b]
__global__ void build_query_kernel(const float* __restrict__ tgt1, const float* __restrict__ pos,
                                   float* __restrict__ out)
{
    int i = blockIdx.x * blockDim.x + threadIdx.x;
    if (i >= MROWS * DIM) return;
    int d = i & 255;
    int r = i >> 8;          // l*B+b
    int l = r / BATCH, b = r % BATCH;
    out[(size_t)(b * NQ + l) * DIM + d] = tgt1[i] + pos[i];
}

// ---------------- self-attention (flash-style, thread-per-query) ----------------
__global__ void attn_kernel(const float* __restrict__ qkv, float* __restrict__ out)
{
    int bh = blockIdx.y;
    int b = bh / NH, h = bh % NH;
    int l = blockIdx.x * 128 + threadIdx.x;
    bool active = (l < NQ);

    float q[DH];
    const float scale = 0.1767766952966369f; // 1/sqrt(32)
    if (active) {
        const float* qp = qkv + (size_t)(l * BATCH + b) * 768 + h * DH;
#pragma unroll
        for (int d = 0; d < DH; d++) q[d] = qp[d] * scale;
    }
    float m = -1e30f, lsum = 0.f;
    float o[DH];
#pragma unroll
    for (int d = 0; d < DH; d++) o[d] = 0.f;

    __shared__ float Ks[32][DH];
    __shared__ float Vs[32][DH];

    for (int m0 = 0; m0 < NQ; m0 += 32) {
        int nk = NQ - m0; if (nk > 32) nk = 32;
        for (int t = threadIdx.x; t < 32 * DH; t += 128) {
            int j = t >> 5, d = t & 31;
            float kv = 0.f, vv = 0.f;
            if (j < nk) {
                const float* row = qkv + (size_t)((m0 + j) * BATCH + b) * 768 + h * DH;
                kv = row[256];
                vv = row[512];
            }
            Ks[j][d] = kv; Vs[j][d] = vv;
        }
        __syncthreads();
        if (active) {
            for (int j = 0; j < nk; j++) {
                float s = 0.f;
#pragma unroll
                for (int d = 0; d < DH; d++) s += q[d] * Ks[j][d];
                float mn = fmaxf(m, s);
                float c = __expf(m - mn);
                float p = __expf(s - mn);
                lsum = lsum * c + p;
#pragma unroll
                for (int d = 0; d < DH; d++) o[d] = o[d] * c + p * Vs[j][d];
                m = mn;
            }
        }
        __syncthreads();
    }
    if (active) {
        float inv = 1.f / lsum;
        float* op = out + (size_t)(l * BATCH + b) * DIM + h * DH;
#pragma unroll
        for (int d = 0; d < DH; d++) op[d] = o[d] * inv;
    }
}

// fix indexing for K/V within attn_kernel loads (row base already offset by h*DH):
// row[256] reads kh element d? -> need row[256 + d_offset]. Handled below via corrected kernel.

// ---------------- MS deformable sampling: warp per (b,q,h) ----------------
__global__ void msdeform_kernel(const float* __restrict__ value,
                                const float* __restrict__ off,
                                const float* __restrict__ aw,
                                const float* __restrict__ refp,
                                float* __restrict__ out)
{
    int gwarp = (blockIdx.x * blockDim.x + threadIdx.x) >> 5;
    int lane  = threadIdx.x & 31;
    if (gwarp >= BATCH * NQ * NH) return;
    int h  = gwarp % NH;
    int bq = gwarp / NH;
    int q  = bq % NQ;
    int b  = bq / NQ;

    const int Hs[4] = {100, 50, 25, 13};
    const int Ws[4] = {150, 75, 38, 19};
    const int St[4] = {0, 15000, 18750, 19700};

    // attention-weight softmax over 16
    const float* awp = aw + (size_t)bq * 128 + h * 16;
    float w16[16];
    float mx = -1e30f;
#pragma unroll
    for (int i = 0; i < 16; i++) { w16[i] = awp[i]; mx = fmaxf(mx, w16[i]); }
    float ssum = 0.f;
#pragma unroll
    for (int i = 0; i < 16; i++) { w16[i] = __expf(w16[i] - mx); ssum += w16[i]; }
    float invs = 1.f / ssum;

    const float* offp = off + (size_t)bq * DIM + h * 32;
    const float* rp   = refp + (size_t)(q * BATCH + b) * NLVL * 4;

    float acc = 0.f;
#pragma unroll
    for (int lv = 0; lv < NLVL; lv++) {
        float r0 = rp[lv*4+0], r1 = rp[lv*4+1], r2 = rp[lv*4+2], r3 = rp[lv*4+3];
        int Wd = Ws[lv], Hh = Hs[lv], st = St[lv];
#pragma unroll
        for (int p = 0; p < NPT; p++) {
            float ox = offp[lv*8 + p*2 + 0];
            float oy = offp[lv*8 + p*2 + 1];
            float locx = r0 + ox * (1.f / NPT) * r2 * 0.5f;
            float locy = r1 + oy * (1.f / NPT) * r3 * 0.5f;
            float x = locx * Wd - 0.5f;
            float y = locy * Hh - 0.5f;
            float x0 = floorf(x), y0 = floorf(y);
            float wq = w16[lv*4 + p] * invs;
            float samp = 0.f;
#pragma unroll
            for (int dy = 0; dy < 2; dy++) {
#pragma unroll
                for (int dx = 0; dx < 2; dx++) {
                    float xi = x0 + dx, yi = y0 + dy;
                    float wbi = (1.f - fabsf(x - xi)) * (1.f - fabsf(y - yi));
                    if (xi >= 0.f && xi < (float)Wd && yi >= 0.f && yi < (float)Hh) {
                        int xc = (int)xi, yc = (int)yi;
                        samp += wbi * value[((size_t)b * STOT + st + yc * Wd + xc) * DIM + h * 32 + lane];
                    }
                }
            }
            acc += wq * samp;
        }
    }
    out[(size_t)bq * DIM + h * 32 + lane] = acc;
}

// ---------------- fused add + layernorm ----------------
// out[row] = LN(X[row] + Y[yrow]); rows indexed (l*B+b). If permNQ, yrow = b*NQ + l.
__global__ void add_ln_kernel(const float* __restrict__ X, const float* __restrict__ Y,
                              const float* __restrict__ g, const float* __restrict__ bta,
                              float* __restrict__ out, int permNQ)
{
    int row = blockIdx.x;
    int d = threadIdx.x;
    int yrow = row;
    if (permNQ) { int l = row / BATCH, b = row % BATCH; yrow = b * NQ + l; }
    float x = X[(size_t)row * DIM + d] + Y[(size_t)yrow * DIM + d];

    __shared__ float red[DIM];
    red[d] = x;
    __syncthreads();
    for (int s = 128; s > 0; s >>= 1) {
        if (d < s) red[d] += red[d + s];
        __syncthreads();
    }
    float mean = red[0] * (1.f / DIM);
    __syncthreads();
    float dx = x - mean;
    red[d] = dx * dx;
    __syncthreads();
    for (int s = 128; s > 0; s >>= 1) {
        if (d < s) red[d] += red[d + s];
        __syncthreads();
    }
    float var = red[0] * (1.f / DIM);
    float r = rsqrtf(var + 1e-5f);
    out[(size_t)row * DIM + d] = dx * r * g[d] + bta[d];
}

// corrected attention kernel (K/V column indexing): replaces attn_kernel above
__global__ void attn_kernel2(const float* __restrict__ qkv, float* __restrict__ out)
{
    int bh = blockIdx.y;
    int b = bh / NH, h = bh % NH;
    int l = blockIdx.x * 128 + threadIdx.x;
    bool active = (l < NQ);

    float q[DH];
    const float scale = 0.1767766952966369f;
    if (active) {
        const float* qp = qkv + (size_t)(l * BATCH + b) * 768 + h * DH;
#pragma unroll
        for (int d = 0; d < DH; d++) q[d] = qp[d] * scale;
    }
    float m = -1e30f, lsum = 0.f;
    float o[DH];
#pragma unroll
    for (int d = 0; d < DH; d++) o[d] = 0.f;

    __shared__ float Ks[32][DH];
    __shared__ float Vs[32][DH];

    for (int m0 = 0; m0 < NQ; m0 += 32) {
        int nk = NQ - m0; if (nk > 32) nk = 32;
        for (int t = threadIdx.x; t < 32 * DH; t += 128) {
            int j = t >> 5, d = t & 31;
            float kv = 0.f, vv = 0.f;
            if (j < nk) {
                const float* row = qkv + (size_t)((m0 + j) * BATCH + b) * 768;
                kv = row[256 + h * DH + d];
                vv = row[512 + h * DH + d];
            }
            Ks[j][d] = kv; Vs[j][d] = vv;
        }
        __syncthreads();
        if (active) {
            for (int j = 0; j < nk; j++) {
                float s = 0.f;
#pragma unroll
                for (int d = 0; d < DH; d++) s += q[d] * Ks[j][d];
                float mn = fmaxf(m, s);
                float c = __expf(m - mn);
                float p = __expf(s - mn);
                lsum = lsum * c + p;
#pragma unroll
                for (int d = 0; d < DH; d++) o[d] = o[d] * c + p * Vs[j][d];
                m = mn;
            }
        }
        __syncthreads();
    }
    if (active) {
        float inv = 1.f / lsum;
        float* op = out + (size_t)(l * BATCH + b) * DIM + h * DH;
#pragma unroll
        for (int d = 0; d < DH; d++) op[d] = o[d] * inv;
    }
}

// ---------------- launch ----------------
extern "C" void kernel_launch(void* const* d_in, const int* in_sizes, int n_in,
                              void* d_out, int out_size)
{
    const float* tgt   = (const float*)d_in[0];
    const float* pos   = (const float*)d_in[1];
    const float* refp  = (const float*)d_in[2];
    const float* mem   = (const float*)d_in[3];
    // d_in[4], d_in[5] : spatial shapes / level starts (compile-time constants)
    const float* in_w  = (const float*)d_in[6];
    const float* in_b  = (const float*)d_in[7];
    const float* sow   = (const float*)d_in[8];
    const float* sob   = (const float*)d_in[9];
    const float* n1g   = (const float*)d_in[10];
    const float* n1b   = (const float*)d_in[11];
    const float* n2g   = (const float*)d_in[12];
    const float* n2b   = (const float*)d_in[13];
    const float* n3g   = (const float*)d_in[14];
    const float* n3b   = (const float*)d_in[15];
    const float* off_w = (const float*)d_in[16];
    const float* off_b = (const float*)d_in[17];
    const float* aw_w  = (const float*)d_in[18];
    const float* aw_b  = (const float*)d_in[19];
    const float* val_w = (const float*)d_in[20];
    const float* val_b = (const float*)d_in[21];
    const float* cow   = (const float*)d_in[22];
    const float* cob   = (const float*)d_in[23];
    const float* l1w   = (const float*)d_in[24];
    const float* l1b   = (const float*)d_in[25];
    const float* l2w   = (const float*)d_in[26];
    const float* l2b   = (const float*)d_in[27];
    float* out = (float*)d_out;

    float *p_q, *p_qkv, *p_ao, *p_b1, *p_t1, *p_qry, *p_val, *p_off, *p_aw, *p_ca, *p_b2, *p_t2, *p_h;
    cudaGetSymbolAddress((void**)&p_q,   g_q);
    cudaGetSymbolAddress((void**)&p_qkv, g_qkv);
    cudaGetSymbolAddress((void**)&p_ao,  g_attn_o);
    cudaGetSymbolAddress((void**)&p_b1,  g_buf1);
    cudaGetSymbolAddress((void**)&p_t1,  g_tgt1);
    cudaGetSymbolAddress((void**)&p_qry, g_query);
    cudaGetSymbolAddress((void**)&p_val, g_value);
    cudaGetSymbolAddress((void**)&p_off, g_off);
    cudaGetSymbolAddress((void**)&p_aw,  g_aw);
    cudaGetSymbolAddress((void**)&p_ca,  g_ca);
    cudaGetSymbolAddress((void**)&p_b2,  g_buf2);
    cudaGetSymbolAddress((void**)&p_t2,  g_tgt2);
    cudaGetSymbolAddress((void**)&p_h,   g_h);

    // 1. q = tgt + pos
    build_q_kernel<<<(MROWS*DIM + 255)/256, 256>>>(tgt, pos, p_q);
    // 2. qh,kh projections (from q), vh (from tgt) -> g_qkv(7200,768)
    sgemm(p_q, in_w,             in_b,       p_qkv, MROWS, 512, DIM, 768, 0,   0, 0, 0);
    sgemm(tgt, in_w + 512*DIM,   in_b + 512, p_qkv, MROWS, 256, DIM, 768, 512, 0, 0, 0);
    // 3. self-attention
    {
        dim3 grid((NQ + 127)/128, BATCH*NH);
        attn_kernel2<<<grid, 128>>>(p_qkv, p_ao);
    }
    // 4. SA out projection + residual LN (norm2)
    sgemm(p_ao, sow, sob, p_b1, MROWS, DIM, DIM, DIM, 0, 0, 0, 0);
    add_ln_kernel<<<MROWS, DIM>>>(tgt, p_b1, n2g, n2b, p_t1, 0);
    // 5. cross-attention inputs
    build_query_kernel<<<(MROWS*DIM + 255)/256, 256>>>(p_t1, pos, p_qry);
    // value projection: out row r=b*S+s from memory row s*B+b
    sgemm(mem, val_w, val_b, p_val, VROWS, DIM, DIM, DIM, 0, STOT, BATCH, 0);
    sgemm(p_qry, off_w, off_b, p_off, MROWS, DIM, DIM, DIM, 0, 0, 0, 0);
    sgemm(p_qry, aw_w,  aw_b,  p_aw,  MROWS, 128, DIM, 128, 0, 0, 0, 0);
    // 6. deformable sampling
    {
        int nwarps = BATCH * NQ * NH;                 // 57600
        int nblocks = (nwarps * 32 + 255) / 256;      // 7200
        msdeform_kernel<<<nblocks, 256>>>(p_val, p_off, p_aw, refp, p_ca);
    }
    // 7. CA out projection + residual LN (norm1, permuted addend)
    sgemm(p_ca, cow, cob, p_b2, MROWS, DIM, DIM, DIM, 0, 0, 0, 0);
    add_ln_kernel<<<MROWS, DIM>>>(p_t1, p_b2, n1g, n1b, p_t2, 1);
    // 8. FFN + LN (norm3)
    sgemm(p_t2, l1w, l1b, p_h,  MROWS, DFF, DIM, DFF, 0, 0, 0, 1);
    sgemm(p_h,  l2w, l2b, p_b1, MROWS, DIM, DFF, DIM, 0, 0, 0, 0);
    add_ln_kernel<<<MROWS, DIM>>>(p_t2, p_b1, n3g, n3b, out, 0);
}

// round 5
// speedup vs baseline: 2.2035x; 2.2035x over previous
#include <cuda_runtime.h>
#include <cstdint>

#define NQ  900
#define BATCH 8
#define DIM 256
#define NH  8
#define DH  32
#define NLVL 4
#define NPT 4
#define DFF 1024
#define STOT 19947

#define MROWS (NQ*BATCH)          // 7200
#define VROWS (BATCH*STOT)        // 159576

#define KVSPLIT 4
#define KVCHUNK 225               // 900 / 4

// ---------------- scratch (device globals; no allocation allowed) ----------------
__device__ float g_q[MROWS*DIM];
__device__ float g_qkv[MROWS*768];        // qh|kh|vh  rows (l*B+b)
__device__ float g_attn_o[MROWS*DIM];
__device__ float g_buf1[MROWS*DIM];
__device__ float g_tgt1[MROWS*DIM];
__device__ float g_query[MROWS*DIM];
__device__ float g_value[(size_t)VROWS*DIM]; // rows (s*B+b)
__device__ float g_off[MROWS*DIM];
__device__ float g_aw[MROWS*128];
__device__ float g_ca[MROWS*DIM];
__device__ float g_buf2[MROWS*DIM];
__device__ float g_tgt2[MROWS*DIM];
__device__ float g_h[MROWS*DFF];
__device__ float g_apart[KVSPLIT * 64 * NQ * DH];   // unnormalized partial O
__device__ float g_aml[KVSPLIT * 64 * NQ * 2];      // (m, lsum) per split

// =========================== helpers ===========================
__device__ __forceinline__ uint32_t smem_u32(const void* p) {
    uint32_t a;
    asm("{ .reg .u64 t; cvta.to.shared.u64 t, %1; cvt.u32.u64 %0, t; }" : "=r"(a) : "l"(p));
    return a;
}
__device__ __forceinline__ void cpa16(uint32_t dst, const float* src, bool pred) {
    int sz = pred ? 16 : 0;
    asm volatile("cp.async.cg.shared.global [%0], [%1], 16, %2;\n" :: "r"(dst), "l"(src), "r"(sz));
}
__device__ __forceinline__ uint32_t f2tf32(float x) {
    uint32_t u;
    asm("cvt.rna.tf32.f32 %0, %1;" : "=r"(u) : "f"(x));
    return u;
}

// =========================== mma.sync tf32 GEMM ===========================
// C[M,N] = A[M,K] @ W[N,K]^T + bias, optional relu. BM=BN=128, BK=32.
// 256 threads = 8 warps in 2(m)x4(n); warp tile 64x32 -> 4 m16-tiles x 4 n8-tiles.
#define BK 32
#define LDAS 36   // padded row (floats)

__global__ void __launch_bounds__(256)
mma_gemm(const float* __restrict__ A, const float* __restrict__ W,
         const float* __restrict__ bias, float* __restrict__ C,
         int M, int N, int K, int ldC, int colOff, int relu)
{
    extern __shared__ float sm[];
    float* Asb[2] = { sm,              sm + 128*LDAS };
    float* Bsb[2] = { sm + 2*128*LDAS, sm + 3*128*LDAS };

    int tid  = threadIdx.x;
    int lane = tid & 31, wid = tid >> 5;
    int warpM = (wid & 1) * 64;
    int warpN = (wid >> 1) * 32;
    int brow = blockIdx.y * 128;
    int bcol = blockIdx.x * 128;

    float acc[4][4][4];
#pragma unroll
    for (int i = 0; i < 4; i++)
#pragma unroll
        for (int j = 0; j < 4; j++)
#pragma unroll
            for (int t = 0; t < 4; t++) acc[i][j][t] = 0.f;

    int nk = K / BK;

    // --- tile loader (cp.async, zero-fill on OOB A rows) ---
    auto load_tile = [&](int i, int buf) {
        int k0 = i * BK;
        uint32_t sA = smem_u32(Asb[buf]);
        uint32_t sB = smem_u32(Bsb[buf]);
#pragma unroll
        for (int it = 0; it < 4; it++) {
            int idx = tid + it * 256;          // 0..1023
            int r = idx >> 3, cc = idx & 7;
            bool okA = (brow + r) < M;
            cpa16(sA + (uint32_t)(r*LDAS + cc*4)*4,
                  A + (size_t)(brow + r) * K + k0 + cc*4, okA);
            cpa16(sB + (uint32_t)(r*LDAS + cc*4)*4,
                  W + (size_t)(bcol + r) * K + k0 + cc*4, true);
        }
        asm volatile("cp.async.commit_group;\n" ::: "memory");
    };

    load_tile(0, 0);

    for (int i = 0; i < nk; i++) {
        if (i + 1 < nk) {
            load_tile(i + 1, (i + 1) & 1);
            asm volatile("cp.async.wait_group 1;\n" ::: "memory");
        } else {
            asm volatile("cp.async.wait_group 0;\n" ::: "memory");
        }
        __syncthreads();

        const float* Bs = Bsb[i & 1];
        uint32_t sAa = smem_u32(Asb[i & 1]);
        int g  = lane >> 3;
        int rw = lane & 7;
        int arow = warpM + ((g & 1) ? 8 : 0) + rw;
        int acolbase = ((g >> 1) ? 4 : 0);

#pragma unroll
        for (int ks = 0; ks < 4; ks++) {
            // B fragments: b0=(k=lane&3, n=lane>>2), b1 at k+4
            uint32_t bf[4][2];
            int kb = ks*8 + (lane & 3);
            int nb = lane >> 2;
#pragma unroll
            for (int j = 0; j < 4; j++) {
                bf[j][0] = f2tf32(Bs[(warpN + j*8 + nb)*LDAS + kb]);
                bf[j][1] = f2tf32(Bs[(warpN + j*8 + nb)*LDAS + kb + 4]);
            }
            int acol = ks*8 + acolbase;
#pragma unroll
            for (int mi = 0; mi < 4; mi++) {
                uint32_t a0, a1, a2, a3;
                uint32_t addr = sAa + (uint32_t)((arow + mi*16)*LDAS + acol)*4;
                asm volatile("ldmatrix.sync.aligned.m8n8.x4.shared.b16 {%0,%1,%2,%3}, [%4];"
                    : "=r"(a0), "=r"(a1), "=r"(a2), "=r"(a3) : "r"(addr));
                a0 = f2tf32(__uint_as_float(a0));
                a1 = f2tf32(__uint_as_float(a1));
                a2 = f2tf32(__uint_as_float(a2));
                a3 = f2tf32(__uint_as_float(a3));
#pragma unroll
                for (int j = 0; j < 4; j++) {
                    asm volatile("mma.sync.aligned.m16n8k8.row.col.f32.tf32.tf32.f32 "
                        "{%0,%1,%2,%3}, {%4,%5,%6,%7}, {%8,%9}, {%0,%1,%2,%3};"
                        : "+f"(acc[mi][j][0]), "+f"(acc[mi][j][1]),
                          "+f"(acc[mi][j][2]), "+f"(acc[mi][j][3])
                        : "r"(a0), "r"(a1), "r"(a2), "r"(a3),
                          "r"(bf[j][0]), "r"(bf[j][1]));
                }
            }
        }
        __syncthreads();
    }

    // --- epilogue: bias (+relu), guarded stores ---
#pragma unroll
    for (int mi = 0; mi < 4; mi++) {
        int r0 = brow + warpM + mi*16 + (lane >> 2);
#pragma unroll
        for (int j = 0; j < 4; j++) {
            int c = warpN + j*8 + (lane & 3)*2;
            float bx = bias[bcol + c], by = bias[bcol + c + 1];
            float2 v0 = make_float2(acc[mi][j][0] + bx, acc[mi][j][1] + by);
            float2 v1 = make_float2(acc[mi][j][2] + bx, acc[mi][j][3] + by);
            if (relu) {
                v0.x = fmaxf(v0.x, 0.f); v0.y = fmaxf(v0.y, 0.f);
                v1.x = fmaxf(v1.x, 0.f); v1.y = fmaxf(v1.y, 0.f);
            }
            if (r0 < M)
                *(float2*)(C + (size_t)r0 * ldC + colOff + bcol + c) = v0;
            if (r0 + 8 < M)
                *(float2*)(C + (size_t)(r0 + 8) * ldC + colOff + bcol + c) = v1;
        }
    }
}

#define GEMM_SMEM (4*128*LDAS*4)   // 73728 bytes

static void gemm(const float* A, const float* W, const float* bias, float* C,
                 int M, int N, int K, int ldC, int colOff, int relu)
{
    dim3 grid(N / 128, (M + 127) / 128);
    mma_gemm<<<grid, 256, GEMM_SMEM>>>(A, W, bias, C, M, N, K, ldC, colOff, relu);
}

// =========================== elementwise ===========================
__global__ void build_q_kernel(const float* __restrict__ a, const float* __restrict__ b,
                               float* __restrict__ out)
{
    int i = blockIdx.x * blockDim.x + threadIdx.x;
    if (i < MROWS * DIM) out[i] = a[i] + b[i];
}

// =========================== self-attention (flash split) ===========================
__global__ void attn_part_kernel(const float* __restrict__ qkv,
                                 float* __restrict__ opart, float* __restrict__ ml)
{
    int split = blockIdx.z;
    int bh = blockIdx.y;
    int b = bh >> 3, h = bh & 7;
    int l = blockIdx.x * 128 + threadIdx.x;
    bool active = (l < NQ);

    float q[DH];
    const float scale = 0.1767766952966369f;
    if (active) {
        const float* qp = qkv + (size_t)(l * BATCH + b) * 768 + h * DH;
#pragma unroll
        for (int d = 0; d < DH; d++) q[d] = qp[d] * scale;
    }
    float m = -1e30f, lsum = 0.f;
    float o[DH];
#pragma unroll
    for (int d = 0; d < DH; d++) o[d] = 0.f;

    __shared__ float Ks[32][DH];
    __shared__ float Vs[32][DH];

    int kbase = split * KVCHUNK;
    for (int m0 = 0; m0 < KVCHUNK; m0 += 32) {
        int nkk = KVCHUNK - m0; if (nkk > 32) nkk = 32;
        for (int t = threadIdx.x; t < 32 * DH; t += 128) {
            int j = t >> 5, d = t & 31;
            float kv = 0.f, vv = 0.f;
            if (j < nkk) {
                const float* row = qkv + (size_t)((kbase + m0 + j) * BATCH + b) * 768;
                kv = row[256 + h * DH + d];
                vv = row[512 + h * DH + d];
            }
            Ks[j][d] = kv; Vs[j][d] = vv;
        }
        __syncthreads();
        if (active) {
            for (int j = 0; j < nkk; j++) {
                float s = 0.f;
#pragma unroll
                for (int d = 0; d < DH; d++) s += q[d] * Ks[j][d];
                float mn = fmaxf(m, s);
                float c = __expf(m - mn);
                float p = __expf(s - mn);
                lsum = lsum * c + p;
#pragma unroll
                for (int d = 0; d < DH; d++) o[d] = o[d] * c + p * Vs[j][d];
                m = mn;
            }
        }
        __syncthreads();
    }
    if (active) {
        size_t idx = ((size_t)(split * 64 + bh) * NQ + l);
        float* op = opart + idx * DH;
#pragma unroll
        for (int d = 0; d < DH; d++) op[d] = o[d];
        ml[idx * 2 + 0] = m;
        ml[idx * 2 + 1] = lsum;
    }
}

__global__ void attn_merge_kernel(const float* __restrict__ opart,
                                  const float* __restrict__ ml,
                                  float* __restrict__ out)
{
    int idx = blockIdx.x * blockDim.x + threadIdx.x;   // (bh*900 + l)*32 + d
    if (idx >= 64 * NQ * DH) return;
    int d  = idx & 31;
    int ql = idx >> 5;            // bh*900 + l
    float mv[KVSPLIT], lv[KVSPLIT];
    float M = -1e30f;
#pragma unroll
    for (int s = 0; s < KVSPLIT; s++) {
        size_t p = ((size_t)s * 64 * NQ + ql) * 2;
        mv[s] = ml[p]; lv[s] = ml[p + 1];
        M = fmaxf(M, mv[s]);
    }
    float den = 0.f, num = 0.f;
#pragma unroll
    for (int s = 0; s < KVSPLIT; s++) {
        float w = __expf(mv[s] - M);
        den += w * lv[s];
        num += w * opart[((size_t)s * 64 * NQ + ql) * DH + d];
    }
    int bh = ql / NQ, l = ql % NQ;
    int b = bh >> 3, h = bh & 7;
    out[((size_t)l * BATCH + b) * DIM + h * DH + d] = num / den;
}

// =========================== MS deformable sampling ===========================
__global__ void msdeform_kernel(const float* __restrict__ value,
                                const float* __restrict__ off,
                                const float* __restrict__ aw,
                                const float* __restrict__ refp,
                                float* __restrict__ out)
{
    int gwarp = (blockIdx.x * blockDim.x + threadIdx.x) >> 5;
    int lane  = threadIdx.x & 31;
    if (gwarp >= MROWS * NH) return;
    int h   = gwarp & 7;
    int row = gwarp >> 3;     // l*B + b
    int b   = row & 7;

    const int Hs[4] = {100, 50, 25, 13};
    const int Ws[4] = {150, 75, 38, 19};
    const int St[4] = {0, 15000, 18750, 19700};

    const float* awp = aw + (size_t)row * 128 + h * 16;
    float w16[16];
    float mx = -1e30f;
#pragma unroll
    for (int i = 0; i < 16; i++) { w16[i] = awp[i]; mx = fmaxf(mx, w16[i]); }
    float ssum = 0.f;
#pragma unroll
    for (int i = 0; i < 16; i++) { w16[i] = __expf(w16[i] - mx); ssum += w16[i]; }
    float invs = 1.f / ssum;

    const float* offp = off + (size_t)row * DIM + h * 32;
    const float* rp   = refp + (size_t)row * NLVL * 4;

    float acc = 0.f;
#pragma unroll
    for (int lv = 0; lv < NLVL; lv++) {
        float r0 = rp[lv*4+0], r1 = rp[lv*4+1], r2 = rp[lv*4+2], r3 = rp[lv*4+3];
        int Wd = Ws[lv], Hh = Hs[lv], st = St[lv];
#pragma unroll
        for (int p = 0; p < NPT; p++) {
            float ox = offp[lv*8 + p*2 + 0];
            float oy = offp[lv*8 + p*2 + 1];
            float locx = r0 + ox * (1.f / NPT) * r2 * 0.5f;
            float locy = r1 + oy * (1.f / NPT) * r3 * 0.5f;
            float x = locx * Wd - 0.5f;
            float y = locy * Hh - 0.5f;
            float x0 = floorf(x), y0 = floorf(y);
            float wq = w16[lv*4 + p] * invs;
            float samp = 0.f;
#pragma unroll
            for (int dy = 0; dy < 2; dy++) {
#pragma unroll
                for (int dx = 0; dx < 2; dx++) {
                    float xi = x0 + dx, yi = y0 + dy;
                    float wbi = (1.f - fabsf(x - xi)) * (1.f - fabsf(y - yi));
                    if (xi >= 0.f && xi < (float)Wd && yi >= 0.f && yi < (float)Hh) {
                        int xc = (int)xi, yc = (int)yi;
                        samp += wbi * value[((size_t)(st + yc * Wd + xc) * BATCH + b) * DIM + h * 32 + lane];
                    }
                }
            }
            acc += wq * samp;
        }
    }
    out[(size_t)row * DIM + h * 32 + lane] = acc;
}

// =========================== fused add + layernorm ===========================
__global__ void add_ln_kernel(const float* __restrict__ X, const float* __restrict__ Y,
                              const float* __restrict__ g, const float* __restrict__ bta,
                              float* __restrict__ out)
{
    int row = blockIdx.x;
    int d = threadIdx.x;
    float x = X[(size_t)row * DIM + d] + Y[(size_t)row * DIM + d];

    __shared__ float red[DIM];
    red[d] = x;
    __syncthreads();
    for (int s = 128; s > 0; s >>= 1) {
        if (d < s) red[d] += red[d + s];
        __syncthreads();
    }
    float mean = red[0] * (1.f / DIM);
    __syncthreads();
    float dx = x - mean;
    red[d] = dx * dx;
    __syncthreads();
    for (int s = 128; s > 0; s >>= 1) {
        if (d < s) red[d] += red[d + s];
        __syncthreads();
    }
    float var = red[0] * (1.f / DIM);
    float r = rsqrtf(var + 1e-5f);
    out[(size_t)row * DIM + d] = dx * r * g[d] + bta[d];
}

// =========================== launch ===========================
extern "C" void kernel_launch(void* const* d_in, const int* in_sizes, int n_in,
                              void* d_out, int out_size)
{
    const float* tgt   = (const float*)d_in[0];
    const float* pos   = (const float*)d_in[1];
    const float* refp  = (const float*)d_in[2];
    const float* mem   = (const float*)d_in[3];
    const float* in_w  = (const float*)d_in[6];
    const float* in_b  = (const float*)d_in[7];
    const float* sow   = (const float*)d_in[8];
    const float* sob   = (const float*)d_in[9];
    const float* n1g   = (const float*)d_in[10];
    const float* n1b   = (const float*)d_in[11];
    const float* n2g   = (const float*)d_in[12];
    const float* n2b   = (const float*)d_in[13];
    const float* n3g   = (const float*)d_in[14];
    const float* n3b   = (const float*)d_in[15];
    const float* off_w = (const float*)d_in[16];
    const float* off_b = (const float*)d_in[17];
    const float* aw_w  = (const float*)d_in[18];
    const float* aw_b  = (const float*)d_in[19];
    const float* val_w = (const float*)d_in[20];
    const float* val_b = (const float*)d_in[21];
    const float* cow   = (const float*)d_in[22];
    const float* cob   = (const float*)d_in[23];
    const float* l1w   = (const float*)d_in[24];
    const float* l1b   = (const float*)d_in[25];
    const float* l2w   = (const float*)d_in[26];
    const float* l2b   = (const float*)d_in[27];
    float* out = (float*)d_out;

    float *p_q, *p_qkv, *p_ao, *p_b1, *p_t1, *p_qry, *p_val, *p_off, *p_aw, *p_ca, *p_b2, *p_t2, *p_h;
    float *p_apart, *p_aml;
    cudaGetSymbolAddress((void**)&p_q,   g_q);
    cudaGetSymbolAddress((void**)&p_qkv, g_qkv);
    cudaGetSymbolAddress((void**)&p_ao,  g_attn_o);
    cudaGetSymbolAddress((void**)&p_b1,  g_buf1);
    cudaGetSymbolAddress((void**)&p_t1,  g_tgt1);
    cudaGetSymbolAddress((void**)&p_qry, g_query);
    cudaGetSymbolAddress((void**)&p_val, g_value);
    cudaGetSymbolAddress((void**)&p_off, g_off);
    cudaGetSymbolAddress((void**)&p_aw,  g_aw);
    cudaGetSymbolAddress((void**)&p_ca,  g_ca);
    cudaGetSymbolAddress((void**)&p_b2,  g_buf2);
    cudaGetSymbolAddress((void**)&p_t2,  g_tgt2);
    cudaGetSymbolAddress((void**)&p_h,   g_h);
    cudaGetSymbolAddress((void**)&p_apart, g_apart);
    cudaGetSymbolAddress((void**)&p_aml,   g_aml);

    cudaFuncSetAttribute(mma_gemm, cudaFuncAttributeMaxDynamicSharedMemorySize, GEMM_SMEM);

    // 1. q = tgt + pos
    build_q_kernel<<<(MROWS*DIM + 255)/256, 256>>>(tgt, pos, p_q);
    // 2. qh,kh from q; vh from tgt
    gemm(p_q, in_w,            in_b,       p_qkv, MROWS, 512, DIM, 768, 0,   0);
    gemm(tgt, in_w + 512*DIM,  in_b + 512, p_qkv, MROWS, 256, DIM, 768, 512, 0);
    // 3. self-attention (flash split + merge)
    {
        dim3 grid((NQ + 127)/128, 64, KVSPLIT);
        attn_part_kernel<<<grid, 128>>>(p_qkv, p_apart, p_aml);
        int tot = 64 * NQ * DH;
        attn_merge_kernel<<<(tot + 255)/256, 256>>>(p_apart, p_aml, p_ao);
    }
    // 4. SA out proj + residual LN (norm2)
    gemm(p_ao, sow, sob, p_b1, MROWS, DIM, DIM, DIM, 0, 0);
    add_ln_kernel<<<MROWS, DIM>>>(tgt, p_b1, n2g, n2b, p_t1);
    // 5. cross-attention inputs
    build_q_kernel<<<(MROWS*DIM + 255)/256, 256>>>(p_t1, pos, p_qry);
    gemm(mem,   val_w, val_b, p_val, VROWS, DIM, DIM, DIM, 0, 0);
    gemm(p_qry, off_w, off_b, p_off, MROWS, DIM, DIM, DIM, 0, 0);
    gemm(p_qry, aw_w,  aw_b,  p_aw,  MROWS, 128, DIM, 128, 0, 0);
    // 6. deformable sampling
    {
        int nwarps = MROWS * NH;
        int nblocks = (nwarps * 32 + 255) / 256;
        msdeform_kernel<<<nblocks, 256>>>(p_val, p_off, p_aw, refp, p_ca);
    }
    // 7. CA out proj + residual LN (norm1)
    gemm(p_ca, cow, cob, p_b2, MROWS, DIM, DIM, DIM, 0, 0);
    add_ln_kernel<<<MROWS, DIM>>>(p_t1, p_b2, n1g, n1b, p_t2);
    // 8. FFN + LN (norm3)
    gemm(p_t2, l1w, l1b, p_h,  MROWS, DFF, DIM, DFF, 0, 1);
    gemm(p_h,  l2w, l2b, p_b1, MROWS, DIM, DFF, DIM, 0, 0);
    add_ln_kernel<<<MROWS, DIM>>>(p_t2, p_b1, n3g, n3b, out);
}

// round 7
// speedup vs baseline: 2.9909x; 1.3574x over previous
#include <cuda_runtime.h>
#include <cstdint>

#define NQ  900
#define BATCH 8
#define DIM 256
#define NH  8
#define DH  32
#define NLVL 4
#define NPT 4
#define DFF 1024
#define STOT 19947

#define MROWS (NQ*BATCH)          // 7200
#define VROWS (BATCH*STOT)        // 159576

// ---------------- scratch (device globals; no allocation allowed) ----------------
__device__ float g_q[MROWS*DIM];
__device__ float g_qkv[MROWS*768];        // qh|kh|vh  rows (l*B+b)
__device__ float g_attn_o[MROWS*DIM];
__device__ float g_buf1[MROWS*DIM];
__device__ float g_tgt1[MROWS*DIM];
__device__ float g_query[MROWS*DIM];
__device__ float g_value[(size_t)VROWS*DIM]; // rows (s*B+b)
__device__ float g_off[MROWS*DIM];
__device__ float g_aw[MROWS*128];
__device__ float g_ca[MROWS*DIM];
__device__ float g_buf2[MROWS*DIM];
__device__ float g_tgt2[MROWS*DIM];
__device__ float g_h[MROWS*DFF];

// =========================== helpers ===========================
__device__ __forceinline__ uint32_t smem_u32(const void* p) {
    uint32_t a;
    asm("{ .reg .u64 t; cvta.to.shared.u64 t, %1; cvt.u32.u64 %0, t; }" : "=r"(a) : "l"(p));
    return a;
}
__device__ __forceinline__ void cpa16(uint32_t dst, const float* src, bool pred) {
    int sz = pred ? 16 : 0;
    asm volatile("cp.async.cg.shared.global [%0], [%1], 16, %2;\n" :: "r"(dst), "l"(src), "r"(sz));
}
__device__ __forceinline__ uint32_t f2tf32(float x) {
    uint32_t u;
    asm("cvt.rna.tf32.f32 %0, %1;" : "=r"(u) : "f"(x));
    return u;
}
#define MMA_TF32(d, a, b) \
    asm volatile("mma.sync.aligned.m16n8k8.row.col.f32.tf32.tf32.f32 " \
        "{%0,%1,%2,%3}, {%4,%5,%6,%7}, {%8,%9}, {%0,%1,%2,%3};" \
        : "+f"((d)[0]), "+f"((d)[1]), "+f"((d)[2]), "+f"((d)[3]) \
        : "r"((a)[0]), "r"((a)[1]), "r"((a)[2]), "r"((a)[3]), "r"((b)[0]), "r"((b)[1]))
#define LDMX4(r0,r1,r2,r3, addr) \
    asm volatile("ldmatrix.sync.aligned.m8n8.x4.shared.b16 {%0,%1,%2,%3}, [%4];" \
        : "=r"(r0), "=r"(r1), "=r"(r2), "=r"(r3) : "r"(addr))

// =========================== mma.sync tf32 GEMM ===========================
#define BK 32
#define LDAS 36   // padded row (floats)

__global__ void __launch_bounds__(256)
mma_gemm(const float* __restrict__ A, const float* __restrict__ W,
         const float* __restrict__ bias, float* __restrict__ C,
         int M, int N, int K, int ldC, int colOff, int relu)
{
    extern __shared__ float sm[];
    float* Asb[2] = { sm,              sm + 128*LDAS };
    float* Bsb[2] = { sm + 2*128*LDAS, sm + 3*128*LDAS };

    int tid  = threadIdx.x;
    int lane = tid & 31, wid = tid >> 5;
    int warpM = (wid & 1) * 64;
    int warpN = (wid >> 1) * 32;
    int brow = blockIdx.y * 128;
    int bcol = blockIdx.x * 128;

    float acc[4][4][4];
#pragma unroll
    for (int i = 0; i < 4; i++)
#pragma unroll
        for (int j = 0; j < 4; j++)
#pragma unroll
            for (int t = 0; t < 4; t++) acc[i][j][t] = 0.f;

    int nk = K / BK;

    auto load_tile = [&](int i, int buf) {
        int k0 = i * BK;
        uint32_t sA = smem_u32(Asb[buf]);
        uint32_t sB = smem_u32(Bsb[buf]);
#pragma unroll
        for (int it = 0; it < 4; it++) {
            int idx = tid + it * 256;
            int r = idx >> 3, cc = idx & 7;
            bool okA = (brow + r) < M;
            cpa16(sA + (uint32_t)(r*LDAS + cc*4)*4,
                  A + (size_t)(brow + r) * K + k0 + cc*4, okA);
            cpa16(sB + (uint32_t)(r*LDAS + cc*4)*4,
                  W + (size_t)(bcol + r) * K + k0 + cc*4, true);
        }
        asm volatile("cp.async.commit_group;\n" ::: "memory");
    };

    load_tile(0, 0);

    for (int i = 0; i < nk; i++) {
        if (i + 1 < nk) {
            load_tile(i + 1, (i + 1) & 1);
            asm volatile("cp.async.wait_group 1;\n" ::: "memory");
        } else {
            asm volatile("cp.async.wait_group 0;\n" ::: "memory");
        }
        __syncthreads();

        const float* Bs = Bsb[i & 1];
        uint32_t sAa = smem_u32(Asb[i & 1]);
        int g  = lane >> 3;
        int rw = lane & 7;
        int arow = warpM + ((g & 1) ? 8 : 0) + rw;
        int acolbase = ((g >> 1) ? 4 : 0);

#pragma unroll
        for (int ks = 0; ks < 4; ks++) {
            uint32_t bf[4][2];
            int kb = ks*8 + (lane & 3);
            int nb = lane >> 2;
#pragma unroll
            for (int j = 0; j < 4; j++) {
                bf[j][0] = f2tf32(Bs[(warpN + j*8 + nb)*LDAS + kb]);
                bf[j][1] = f2tf32(Bs[(warpN + j*8 + nb)*LDAS + kb + 4]);
            }
            int acol = ks*8 + acolbase;
#pragma unroll
            for (int mi = 0; mi < 4; mi++) {
                uint32_t a[4];
                uint32_t addr = sAa + (uint32_t)((arow + mi*16)*LDAS + acol)*4;
                LDMX4(a[0], a[1], a[2], a[3], addr);
                a[0] = f2tf32(__uint_as_float(a[0]));
                a[1] = f2tf32(__uint_as_float(a[1]));
                a[2] = f2tf32(__uint_as_float(a[2]));
                a[3] = f2tf32(__uint_as_float(a[3]));
#pragma unroll
                for (int j = 0; j < 4; j++) MMA_TF32(acc[mi][j], a, bf[j]);
            }
        }
        __syncthreads();
    }

#pragma unroll
    for (int mi = 0; mi < 4; mi++) {
        int r0 = brow + warpM + mi*16 + (lane >> 2);
#pragma unroll
        for (int j = 0; j < 4; j++) {
            int c = warpN + j*8 + (lane & 3)*2;
            float bx = bias[bcol + c], by = bias[bcol + c + 1];
            float2 v0 = make_float2(acc[mi][j][0] + bx, acc[mi][j][1] + by);
            float2 v1 = make_float2(acc[mi][j][2] + bx, acc[mi][j][3] + by);
            if (relu) {
                v0.x = fmaxf(v0.x, 0.f); v0.y = fmaxf(v0.y, 0.f);
                v1.x = fmaxf(v1.x, 0.f); v1.y = fmaxf(v1.y, 0.f);
            }
            if (r0 < M)
                *(float2*)(C + (size_t)r0 * ldC + colOff + bcol + c) = v0;
            if (r0 + 8 < M)
                *(float2*)(C + (size_t)(r0 + 8) * ldC + colOff + bcol + c) = v1;
        }
    }
}

#define GEMM_SMEM (4*128*LDAS*4)   // 73728 bytes

static void gemm(const float* A, const float* W, const float* bias, float* C,
                 int M, int N, int K, int ldC, int colOff, int relu)
{
    dim3 grid(N / 128, (M + 127) / 128);
    mma_gemm<<<grid, 256, GEMM_SMEM>>>(A, W, bias, C, M, N, K, ldC, colOff, relu);
}

// =========================== elementwise ===========================
__global__ void build_q_kernel(const float* __restrict__ a, const float* __restrict__ b,
                               float* __restrict__ out)
{
    int i = blockIdx.x * blockDim.x + threadIdx.x;
    if (i < MROWS * DIM) out[i] = a[i] + b[i];
}

// =========================== mma flash self-attention ===========================
// grid (8 qtiles, 64 bh), 128 threads. Q tile 128x32 in reg fragments.
// Loop K tiles of 64: S=Q@K^T, online softmax, P@V through smem ldmatrix.
#define ATT_LQ 36     // Q/K/V smem pitch
#define ATT_LP 68     // P smem pitch
#define ATT_SMEM ((128*ATT_LQ + 64*ATT_LQ + 64*ATT_LQ + 128*ATT_LP)*4)   // 71680 B

__global__ void __launch_bounds__(128)
attn_mma_kernel(const float* __restrict__ qkv, float* __restrict__ out)
{
    extern __shared__ float sm[];
    float* Qs = sm;                      // 128 x 36
    float* Ks = Qs + 128*ATT_LQ;         // 64 x 36
    float* Vs = Ks + 64*ATT_LQ;          // 64 x 36
    float* Ps = Vs + 64*ATT_LQ;          // 128 x 68

    int tid = threadIdx.x, lane = tid & 31, wid = tid >> 5;
    int qt = blockIdx.x, bh = blockIdx.y;
    int b = bh >> 3, h = bh & 7;
    int warpM = wid * 32;

    // ---- load Q tile (scaled), zero-fill OOB rows ----
    const float scale = 0.1767766952966369f;
    for (int s = tid; s < 128*8; s += 128) {
        int r = s >> 3, seg = s & 7;
        int l = qt*128 + r;
        float4 v = make_float4(0.f, 0.f, 0.f, 0.f);
        if (l < NQ) v = *(const float4*)(qkv + (size_t)(l*8 + b)*768 + h*32 + seg*4);
        v.x *= scale; v.y *= scale; v.z *= scale; v.w *= scale;
        *(float4*)(Qs + r*ATT_LQ + seg*4) = v;
    }
    __syncthreads();

    // ---- Q fragments (held in registers for whole kernel) ----
    int g = lane >> 3, rw = lane & 7;
    int frow = (g & 1) * 8 + rw;
    int fcol = (g >> 1) * 4;
    uint32_t qa[2][4][4];
#pragma unroll
    for (int mi = 0; mi < 2; mi++)
#pragma unroll
        for (int ks = 0; ks < 4; ks++) {
            uint32_t addr = smem_u32(Qs + (warpM + mi*16 + frow)*ATT_LQ + ks*8 + fcol);
            uint32_t a0, a1, a2, a3;
            LDMX4(a0, a1, a2, a3, addr);
            qa[mi][ks][0] = f2tf32(__uint_as_float(a0));
            qa[mi][ks][1] = f2tf32(__uint_as_float(a1));
            qa[mi][ks][2] = f2tf32(__uint_as_float(a2));
            qa[mi][ks][3] = f2tf32(__uint_as_float(a3));
        }

    float oacc[2][4][4];
#pragma unroll
    for (int mi = 0; mi < 2; mi++)
#pragma unroll
        for (int j = 0; j < 4; j++)
#pragma unroll
            for (int t = 0; t < 4; t++) oacc[mi][j][t] = 0.f;
    float mrow[2][2] = {{-1e30f, -1e30f}, {-1e30f, -1e30f}};
    float lrow[2][2] = {{0.f, 0.f}, {0.f, 0.f}};

    const int NT = (NQ + 63) / 64;   // 15
    for (int kt = 0; kt < NT; kt++) {
        __syncthreads();   // previous tile's smem use done
        // ---- load K/V tile, zero-fill invalid keys ----
        for (int s = tid; s < 64*8; s += 128) {
            int r = s >> 3, seg = s & 7;
            int key = kt*64 + r;
            float4 kv = make_float4(0.f,0.f,0.f,0.f), vv = kv;
            if (key < NQ) {
                const float* base = qkv + (size_t)(key*8 + b)*768 + h*32;
                kv = *(const float4*)(base + 256 + seg*4);
                vv = *(const float4*)(base + 512 + seg*4);
            }
            *(float4*)(Ks + r*ATT_LQ + seg*4) = kv;
            *(float4*)(Vs + r*ATT_LQ + seg*4) = vv;
        }
        __syncthreads();

        // ---- S = Q @ K^T (128 x 64) ----
        float acc[2][8][4];
#pragma unroll
        for (int mi = 0; mi < 2; mi++)
#pragma unroll
            for (int j = 0; j < 8; j++)
#pragma unroll
                for (int t = 0; t < 4; t++) acc[mi][j][t] = 0.f;
#pragma unroll
        for (int ks = 0; ks < 4; ks++) {
            uint32_t bf[8][2];
            int kb = ks*8 + (lane & 3);
            int nb = lane >> 2;
#pragma unroll
            for (int j = 0; j < 8; j++) {
                bf[j][0] = f2tf32(Ks[(j*8 + nb)*ATT_LQ + kb]);
                bf[j][1] = f2tf32(Ks[(j*8 + nb)*ATT_LQ + kb + 4]);
            }
#pragma unroll
            for (int mi = 0; mi < 2; mi++)
#pragma unroll
                for (int j = 0; j < 8; j++) MMA_TF32(acc[mi][j], qa[mi][ks], bf[j]);
        }

        // ---- mask invalid keys ----
        int keyb = kt*64 + 2*(lane & 3);
#pragma unroll
        for (int j = 0; j < 8; j++) {
            if (keyb + j*8 >= NQ) {
#pragma unroll
                for (int mi = 0; mi < 2; mi++) {
                    acc[mi][j][0] = -1e30f; acc[mi][j][1] = -1e30f;
                    acc[mi][j][2] = -1e30f; acc[mi][j][3] = -1e30f;
                }
            }
        }

        // ---- online softmax per row instance ----
#pragma unroll
        for (int mi = 0; mi < 2; mi++) {
#pragma unroll
            for (int inst = 0; inst < 2; inst++) {
                int i0 = inst*2;
                float mx = -1e30f;
#pragma unroll
                for (int j = 0; j < 8; j++)
                    mx = fmaxf(mx, fmaxf(acc[mi][j][i0], acc[mi][j][i0+1]));
                mx = fmaxf(mx, __shfl_xor_sync(0xffffffff, mx, 1));
                mx = fmaxf(mx, __shfl_xor_sync(0xffffffff, mx, 2));
                float mo = mrow[mi][inst];
                float mn = fmaxf(mo, mx);
                float c = __expf(mo - mn);
                float sum = 0.f;
#pragma unroll
                for (int j = 0; j < 8; j++) {
                    float p0 = __expf(acc[mi][j][i0]   - mn);
                    float p1 = __expf(acc[mi][j][i0+1] - mn);
                    acc[mi][j][i0] = p0; acc[mi][j][i0+1] = p1;
                    sum += p0 + p1;
                }
                sum += __shfl_xor_sync(0xffffffff, sum, 1);
                sum += __shfl_xor_sync(0xffffffff, sum, 2);
                lrow[mi][inst] = lrow[mi][inst] * c + sum;
                mrow[mi][inst] = mn;
#pragma unroll
                for (int j2 = 0; j2 < 4; j2++) {
                    oacc[mi][j2][i0]   *= c;
                    oacc[mi][j2][i0+1] *= c;
                }
            }
        }

        // ---- store P to smem (own warp rows only) ----
        int pr = lane >> 2, pc = 2*(lane & 3);
#pragma unroll
        for (int mi = 0; mi < 2; mi++)
#pragma unroll
            for (int j = 0; j < 8; j++) {
                *(float2*)(Ps + (warpM + mi*16 + pr)*ATT_LP + j*8 + pc)
                    = make_float2(acc[mi][j][0], acc[mi][j][1]);
                *(float2*)(Ps + (warpM + mi*16 + pr + 8)*ATT_LP + j*8 + pc)
                    = make_float2(acc[mi][j][2], acc[mi][j][3]);
            }
        __syncwarp();

        // ---- O += P @ V ----
#pragma unroll
        for (int ks2 = 0; ks2 < 8; ks2++) {
            uint32_t bv[4][2];
            int kb2 = ks2*8 + (lane & 3);
            int nb2 = lane >> 2;
#pragma unroll
            for (int j2 = 0; j2 < 4; j2++) {
                bv[j2][0] = f2tf32(Vs[kb2*ATT_LQ + j2*8 + nb2]);
                bv[j2][1] = f2tf32(Vs[(kb2+4)*ATT_LQ + j2*8 + nb2]);
            }
#pragma unroll
            for (int mi = 0; mi < 2; mi++) {
                uint32_t pa[4];
                uint32_t addr = smem_u32(Ps + (warpM + mi*16 + frow)*ATT_LP + ks2*8 + fcol);
                LDMX4(pa[0], pa[1], pa[2], pa[3], addr);
                pa[0] = f2tf32(__uint_as_float(pa[0]));
                pa[1] = f2tf32(__uint_as_float(pa[1]));
                pa[2] = f2tf32(__uint_as_float(pa[2]));
                pa[3] = f2tf32(__uint_as_float(pa[3]));
#pragma unroll
                for (int j2 = 0; j2 < 4; j2++) MMA_TF32(oacc[mi][j2], pa, bv[j2]);
            }
        }
    }

    // ---- epilogue: normalize, store ----
#pragma unroll
    for (int mi = 0; mi < 2; mi++)
#pragma unroll
        for (int inst = 0; inst < 2; inst++) {
            float inv = 1.f / lrow[mi][inst];
            int r = qt*128 + warpM + mi*16 + (lane >> 2) + inst*8;
            if (r < NQ) {
                float* op = out + ((size_t)r*8 + b)*DIM + h*32;
                int i0 = inst*2;
#pragma unroll
                for (int j2 = 0; j2 < 4; j2++) {
                    *(float2*)(op + j2*8 + 2*(lane & 3))
                        = make_float2(oacc[mi][j2][i0]*inv, oacc[mi][j2][i0+1]*inv);
                }
            }
        }
}

// =========================== MS deformable sampling ===========================
__global__ void msdeform_kernel(const float* __restrict__ value,
                                const float* __restrict__ off,
                                const float* __restrict__ aw,
                                const float* __restrict__ refp,
                                float* __restrict__ out)
{
    int gwarp = (blockIdx.x * blockDim.x + threadIdx.x) >> 5;
    int lane  = threadIdx.x & 31;
    if (gwarp >= MROWS * NH) return;
    int h   = gwarp & 7;
    int row = gwarp >> 3;     // l*B + b
    int b   = row & 7;

    const int Hs[4] = {100, 50, 25, 13};
    const int Ws[4] = {150, 75, 38, 19};
    const int St[4] = {0, 15000, 18750, 19700};

    const float* awp = aw + (size_t)row * 128 + h * 16;
    float w16[16];
    float mx = -1e30f;
#pragma unroll
    for (int i = 0; i < 16; i++) { w16[i] = awp[i]; mx = fmaxf(mx, w16[i]); }
    float ssum = 0.f;
#pragma unroll
    for (int i = 0; i < 16; i++) { w16[i] = __expf(w16[i] - mx); ssum += w16[i]; }
    float invs = 1.f / ssum;

    const float* offp = off + (size_t)row * DIM + h * 32;
    const float* rp   = refp + (size_t)row * NLVL * 4;

    float acc = 0.f;
#pragma unroll
    for (int lv = 0; lv < NLVL; lv++) {
        float r0 = rp[lv*4+0], r1 = rp[lv*4+1], r2 = rp[lv*4+2], r3 = rp[lv*4+3];
        int Wd = Ws[lv], Hh = Hs[lv], st = St[lv];
#pragma unroll
        for (int p = 0; p < NPT; p++) {
            float ox = offp[lv*8 + p*2 + 0];
            float oy = offp[lv*8 + p*2 + 1];
            float locx = r0 + ox * (1.f / NPT) * r2 * 0.5f;
            float locy = r1 + oy * (1.f / NPT) * r3 * 0.5f;
            float x = locx * Wd - 0.5f;
            float y = locy * Hh - 0.5f;
            float x0 = floorf(x), y0 = floorf(y);
            float wq = w16[lv*4 + p] * invs;
            float samp = 0.f;
#pragma unroll
            for (int dy = 0; dy < 2; dy++) {
#pragma unroll
                for (int dx = 0; dx < 2; dx++) {
                    float xi = x0 + dx, yi = y0 + dy;
                    float wbi = (1.f - fabsf(x - xi)) * (1.f - fabsf(y - yi));
                    if (xi >= 0.f && xi < (float)Wd && yi >= 0.f && yi < (float)Hh) {
                        int xc = (int)xi, yc = (int)yi;
                        samp += wbi * value[((size_t)(st + yc * Wd + xc) * BATCH + b) * DIM + h * 32 + lane];
                    }
                }
            }
            acc += wq * samp;
        }
    }
    out[(size_t)row * DIM + h * 32 + lane] = acc;
}

// =========================== fused add + layernorm ===========================
__global__ void add_ln_kernel(const float* __restrict__ X, const float* __restrict__ Y,
                              const float* __restrict__ g, const float* __restrict__ bta,
                              float* __restrict__ out)
{
    int row = blockIdx.x;
    int d = threadIdx.x;
    float x = X[(size_t)row * DIM + d] + Y[(size_t)row * DIM + d];

    __shared__ float red[DIM];
    red[d] = x;
    __syncthreads();
    for (int s = 128; s > 0; s >>= 1) {
        if (d < s) red[d] += red[d + s];
        __syncthreads();
    }
    float mean = red[0] * (1.f / DIM);
    __syncthreads();
    float dx = x - mean;
    red[d] = dx * dx;
    __syncthreads();
    for (int s = 128; s > 0; s >>= 1) {
        if (d < s) red[d] += red[d + s];
        __syncthreads();
    }
    float var = red[0] * (1.f / DIM);
    float r = rsqrtf(var + 1e-5f);
    out[(size_t)row * DIM + d] = dx * r * g[d] + bta[d];
}

// =========================== launch ===========================
extern "C" void kernel_launch(void* const* d_in, const int* in_sizes, int n_in,
                              void* d_out, int out_size)
{
    const float* tgt   = (const float*)d_in[0];
    const float* pos   = (const float*)d_in[1];
    const float* refp  = (const float*)d_in[2];
    const float* mem   = (const float*)d_in[3];
    const float* in_w  = (const float*)d_in[6];
    const float* in_b  = (const float*)d_in[7];
    const float* sow   = (const float*)d_in[8];
    const float* sob   = (const float*)d_in[9];
    const float* n1g   = (const float*)d_in[10];
    const float* n1b   = (const float*)d_in[11];
    const float* n2g   = (const float*)d_in[12];
    const float* n2b   = (const float*)d_in[13];
    const float* n3g   = (const float*)d_in[14];
    const float* n3b   = (const float*)d_in[15];
    const float* off_w = (const float*)d_in[16];
    const float* off_b = (const float*)d_in[17];
    const float* aw_w  = (const float*)d_in[18];
    const float* aw_b  = (const float*)d_in[19];
    const float* val_w = (const float*)d_in[20];
    const float* val_b = (const float*)d_in[21];
    const float* cow   = (const float*)d_in[22];
    const float* cob   = (const float*)d_in[23];
    const float* l1w   = (const float*)d_in[24];
    const float* l1b   = (const float*)d_in[25];
    const float* l2w   = (const float*)d_in[26];
    const float* l2b   = (const float*)d_in[27];
    float* out = (float*)d_out;

    float *p_q, *p_qkv, *p_ao, *p_b1, *p_t1, *p_qry, *p_val, *p_off, *p_aw, *p_ca, *p_b2, *p_t2, *p_h;
    cudaGetSymbolAddress((void**)&p_q,   g_q);
    cudaGetSymbolAddress((void**)&p_qkv, g_qkv);
    cudaGetSymbolAddress((void**)&p_ao,  g_attn_o);
    cudaGetSymbolAddress((void**)&p_b1,  g_buf1);
    cudaGetSymbolAddress((void**)&p_t1,  g_tgt1);
    cudaGetSymbolAddress((void**)&p_qry, g_query);
    cudaGetSymbolAddress((void**)&p_val, g_value);
    cudaGetSymbolAddress((void**)&p_off, g_off);
    cudaGetSymbolAddress((void**)&p_aw,  g_aw);
    cudaGetSymbolAddress((void**)&p_ca,  g_ca);
    cudaGetSymbolAddress((void**)&p_b2,  g_buf2);
    cudaGetSymbolAddress((void**)&p_t2,  g_tgt2);
    cudaGetSymbolAddress((void**)&p_h,   g_h);

    cudaFuncSetAttribute(mma_gemm, cudaFuncAttributeMaxDynamicSharedMemorySize, GEMM_SMEM);
    cudaFuncSetAttribute(attn_mma_kernel, cudaFuncAttributeMaxDynamicSharedMemorySize, ATT_SMEM);

    // 1. q = tgt + pos
    build_q_kernel<<<(MROWS*DIM + 255)/256, 256>>>(tgt, pos, p_q);
    // 2. qh,kh from q; vh from tgt
    gemm(p_q, in_w,            in_b,       p_qkv, MROWS, 512, DIM, 768, 0,   0);
    gemm(tgt, in_w + 512*DIM,  in_b + 512, p_qkv, MROWS, 256, DIM, 768, 512, 0);
    // 3. self-attention (mma flash)
    {
        dim3 grid(8, 64);
        attn_mma_kernel<<<grid, 128, ATT_SMEM>>>(p_qkv, p_ao);
    }
    // 4. SA out proj + residual LN (norm2)
    gemm(p_ao, sow, sob, p_b1, MROWS, DIM, DIM, DIM, 0, 0);
    add_ln_kernel<<<MROWS, DIM>>>(tgt, p_b1, n2g, n2b, p_t1);
    // 5. cross-attention inputs
    build_q_kernel<<<(MROWS*DIM + 255)/256, 256>>>(p_t1, pos, p_qry);
    gemm(mem,   val_w, val_b, p_val, VROWS, DIM, DIM, DIM, 0, 0);
    gemm(p_qry, off_w, off_b, p_off, MROWS, DIM, DIM, DIM, 0, 0);
    gemm(p_qry, aw_w,  aw_b,  p_aw,  MROWS, 128, DIM, 128, 0, 0);
    // 6. deformable sampling
    {
        int nwarps = MROWS * NH;
        int nblocks = (nwarps * 32 + 255) / 256;
        msdeform_kernel<<<nblocks, 256>>>(p_val, p_off, p_aw, refp, p_ca);
    }
    // 7. CA out proj + residual LN (norm1)
    gemm(p_ca, cow, cob, p_b2, MROWS, DIM, DIM, DIM, 0, 0);
    add_ln_kernel<<<MROWS, DIM>>>(p_t1, p_b2, n1g, n1b, p_t2);
    // 8. FFN + LN (norm3)
    gemm(p_t2, l1w, l1b, p_h,  MROWS, DFF, DIM, DFF, 0, 1);
    gemm(p_h,  l2w, l2b, p_b1, MROWS, DIM, DFF, DIM, 0, 0);
    add_ln_kernel<<<MROWS, DIM>>>(p_t2, p_b1, n3g, n3b, out);
}

// round 16
// speedup vs baseline: 3.1921x; 1.0673x over previous
#include <cuda_runtime.h>
#include <cstdint>

#define NQ  900
#define BATCH 8
#define DIM 256
#define NH  8
#define DH  32
#define NLVL 4
#define NPT 4
#define DFF 1024
#define STOT 19947

#define MROWS (NQ*BATCH)          // 7200
#define VROWS (BATCH*STOT)        // 159576

// ---------------- scratch (device globals; no allocation allowed) ----------------
__device__ float g_q[MROWS*DIM];
__device__ float g_qkv[MROWS*768];        // qh|kh|vh  rows (l*B+b)
__device__ float g_attn_o[MROWS*DIM];
__device__ float g_buf1[MROWS*DIM];
__device__ float g_tgt1[MROWS*DIM];
__device__ float g_query[MROWS*DIM];
__device__ float g_value[(size_t)VROWS*DIM]; // rows (s*B+b)
__device__ float g_off[MROWS*DIM];
__device__ float g_aw[MROWS*128];
__device__ float g_ca[MROWS*DIM];
__device__ float g_buf2[MROWS*DIM];
__device__ float g_tgt2[MROWS*DIM];
__device__ float g_h[MROWS*DFF];

// =========================== helpers ===========================
__device__ __forceinline__ uint32_t smem_u32(const void* p) {
    uint32_t a;
    asm("{ .reg .u64 t; cvta.to.shared.u64 t, %1; cvt.u32.u64 %0, t; }" : "=r"(a) : "l"(p));
    return a;
}
__device__ __forceinline__ void cpa16(uint32_t dst, const float* src, bool pred) {
    int sz = pred ? 16 : 0;
    asm volatile("cp.async.cg.shared.global [%0], [%1], 16, %2;\n" :: "r"(dst), "l"(src), "r"(sz));
}
// NOTE: mma.sync tf32 ignores the low 13 mantissa bits of the operand register,
// so we feed raw fp32 bits (truncation) and skip cvt.rna.tf32 entirely.
#define MMA_TF32(d, a, b) \
    asm volatile("mma.sync.aligned.m16n8k8.row.col.f32.tf32.tf32.f32 " \
        "{%0,%1,%2,%3}, {%4,%5,%6,%7}, {%8,%9}, {%0,%1,%2,%3};" \
        : "+f"((d)[0]), "+f"((d)[1]), "+f"((d)[2]), "+f"((d)[3]) \
        : "r"((a)[0]), "r"((a)[1]), "r"((a)[2]), "r"((a)[3]), "r"((b)[0]), "r"((b)[1]))
#define LDMX4(r0,r1,r2,r3, addr) \
    asm volatile("ldmatrix.sync.aligned.m8n8.x4.shared.b16 {%0,%1,%2,%3}, [%4];" \
        : "=r"(r0), "=r"(r1), "=r"(r2), "=r"(r3) : "r"(addr))

// =========================== mma.sync tf32 GEMM ===========================
#define BK 32
#define LDAS 36   // padded row (floats)

__global__ void __launch_bounds__(256)
mma_gemm(const float* __restrict__ A, const float* __restrict__ W,
         const float* __restrict__ bias, float* __restrict__ C,
         int M, int N, int K, int ldC, int colOff, int relu)
{
    extern __shared__ float sm[];
    float* Asb[2] = { sm,              sm + 128*LDAS };
    float* Bsb[2] = { sm + 2*128*LDAS, sm + 3*128*LDAS };

    int tid  = threadIdx.x;
    int lane = tid & 31, wid = tid >> 5;
    int warpM = (wid & 1) * 64;
    int warpN = (wid >> 1) * 32;
    int brow = blockIdx.y * 128;
    int bcol = blockIdx.x * 128;

    float acc[4][4][4];
#pragma unroll
    for (int i = 0; i < 4; i++)
#pragma unroll
        for (int j = 0; j < 4; j++)
#pragma unroll
            for (int t = 0; t < 4; t++) acc[i][j][t] = 0.f;

    int nk = K / BK;

    auto load_tile = [&](int i, int buf) {
        int k0 = i * BK;
        uint32_t sA = smem_u32(Asb[buf]);
        uint32_t sB = smem_u32(Bsb[buf]);
#pragma unroll
        for (int it = 0; it < 4; it++) {
            int idx = tid + it * 256;
            int r = idx >> 3, cc = idx & 7;
            bool okA = (brow + r) < M;
            cpa16(sA + (uint32_t)(r*LDAS + cc*4)*4,
                  A + (size_t)(brow + r) * K + k0 + cc*4, okA);
            cpa16(sB + (uint32_t)(r*LDAS + cc*4)*4,
                  W + (size_t)(bcol + r) * K + k0 + cc*4, true);
        }
        asm volatile("cp.async.commit_group;\n" ::: "memory");
    };

    load_tile(0, 0);

    for (int i = 0; i < nk; i++) {
        if (i + 1 < nk) {
            load_tile(i + 1, (i + 1) & 1);
            asm volatile("cp.async.wait_group 1;\n" ::: "memory");
        } else {
            asm volatile("cp.async.wait_group 0;\n" ::: "memory");
        }
        __syncthreads();

        const uint32_t* Bs = (const uint32_t*)Bsb[i & 1];
        uint32_t sAa = smem_u32(Asb[i & 1]);
        int g  = lane >> 3;
        int rw = lane & 7;
        int arow = warpM + ((g & 1) ? 8 : 0) + rw;
        int acolbase = ((g >> 1) ? 4 : 0);

#pragma unroll
        for (int ks = 0; ks < 4; ks++) {
            uint32_t bf[4][2];
            int kb = ks*8 + (lane & 3);
            int nb = lane >> 2;
#pragma unroll
            for (int j = 0; j < 4; j++) {
                bf[j][0] = Bs[(warpN + j*8 + nb)*LDAS + kb];
                bf[j][1] = Bs[(warpN + j*8 + nb)*LDAS + kb + 4];
            }
            int acol = ks*8 + acolbase;
#pragma unroll
            for (int mi = 0; mi < 4; mi++) {
                uint32_t a[4];
                uint32_t addr = sAa + (uint32_t)((arow + mi*16)*LDAS + acol)*4;
                LDMX4(a[0], a[1], a[2], a[3], addr);
#pragma unroll
                for (int j = 0; j < 4; j++) MMA_TF32(acc[mi][j], a, bf[j]);
            }
        }
        __syncthreads();
    }

#pragma unroll
    for (int mi = 0; mi < 4; mi++) {
        int r0 = brow + warpM + mi*16 + (lane >> 2);
#pragma unroll
        for (int j = 0; j < 4; j++) {
            int c = warpN + j*8 + (lane & 3)*2;
            float bx = bias[bcol + c], by = bias[bcol + c + 1];
            float2 v0 = make_float2(acc[mi][j][0] + bx, acc[mi][j][1] + by);
            float2 v1 = make_float2(acc[mi][j][2] + bx, acc[mi][j][3] + by);
            if (relu) {
                v0.x = fmaxf(v0.x, 0.f); v0.y = fmaxf(v0.y, 0.f);
                v1.x = fmaxf(v1.x, 0.f); v1.y = fmaxf(v1.y, 0.f);
            }
            if (r0 < M)
                *(float2*)(C + (size_t)r0 * ldC + colOff + bcol + c) = v0;
            if (r0 + 8 < M)
                *(float2*)(C + (size_t)(r0 + 8) * ldC + colOff + bcol + c) = v1;
        }
    }
}

#define GEMM_SMEM (4*128*LDAS*4)   // 73728 bytes

static void gemm(const float* A, const float* W, const float* bias, float* C,
                 int M, int N, int K, int ldC, int colOff, int relu)
{
    dim3 grid(N / 128, (M + 127) / 128);
    mma_gemm<<<grid, 256, GEMM_SMEM>>>(A, W, bias, C, M, N, K, ldC, colOff, relu);
}

// =========================== elementwise ===========================
__global__ void build_q_kernel(const float* __restrict__ a, const float* __restrict__ b,
                               float* __restrict__ out)
{
    int i = blockIdx.x * blockDim.x + threadIdx.x;
    if (i < MROWS * DIM) out[i] = a[i] + b[i];
}

// =========================== mma flash self-attention ===========================
// grid (8 qtiles, 64 bh), 128 threads. Q tile 128x32 in reg fragments.
// Ps reuses the Qs staging region (Q fragments are register-resident after startup).
#define ATT_LQ 36     // Q/K/V smem pitch
#define ATT_LP 68     // P smem pitch
#define ATT_SMEM ((128*ATT_LP + 64*ATT_LQ + 64*ATT_LQ)*4)   // 53248 B

__global__ void __launch_bounds__(128, 4)
attn_mma_kernel(const float* __restrict__ qkv, float* __restrict__ out)
{
    extern __shared__ float sm[];
    float* Qs = sm;                      // 128 x 36 (staging, dies after frag load)
    float* Ps = sm;                      // 128 x 68 (same region, reused)
    float* Ks = sm + 128*ATT_LP;         // 64 x 36
    float* Vs = Ks + 64*ATT_LQ;          // 64 x 36

    int tid = threadIdx.x, lane = tid & 31, wid = tid >> 5;
    int qt = blockIdx.x, bh = blockIdx.y;
    int b = bh >> 3, h = bh & 7;
    int warpM = wid * 32;

    // ---- load Q tile (scaled), zero-fill OOB rows ----
    const float scale = 0.1767766952966369f;
    for (int s = tid; s < 128*8; s += 128) {
        int r = s >> 3, seg = s & 7;
        int l = qt*128 + r;
        float4 v = make_float4(0.f, 0.f, 0.f, 0.f);
        if (l < NQ) v = *(const float4*)(qkv + (size_t)(l*8 + b)*768 + h*32 + seg*4);
        v.x *= scale; v.y *= scale; v.z *= scale; v.w *= scale;
        *(float4*)(Qs + r*ATT_LQ + seg*4) = v;
    }
    __syncthreads();

    // ---- Q fragments (registers for whole kernel; raw fp32 bits as tf32) ----
    int g = lane >> 3, rw = lane & 7;
    int frow = (g & 1) * 8 + rw;
    int fcol = (g >> 1) * 4;
    uint32_t qa[2][4][4];
#pragma unroll
    for (int mi = 0; mi < 2; mi++)
#pragma unroll
        for (int ks = 0; ks < 4; ks++) {
            uint32_t addr = smem_u32(Qs + (warpM + mi*16 + frow)*ATT_LQ + ks*8 + fcol);
            LDMX4(qa[mi][ks][0], qa[mi][ks][1], qa[mi][ks][2], qa[mi][ks][3], addr);
        }

    float oacc[2][4][4];
#pragma unroll
    for (int mi = 0; mi < 2; mi++)
#pragma unroll
        for (int j = 0; j < 4; j++)
#pragma unroll
            for (int t = 0; t < 4; t++) oacc[mi][j][t] = 0.f;
    float mrow[2][2] = {{-1e30f, -1e30f}, {-1e30f, -1e30f}};
    float lrow[2][2] = {{0.f, 0.f}, {0.f, 0.f}};

    const int NT = (NQ + 63) / 64;   // 15
    for (int kt = 0; kt < NT; kt++) {
        __syncthreads();   // previous tile's smem use done (also fences Qs->Ps reuse)
        // ---- load K/V tile, zero-fill invalid keys ----
        for (int s = tid; s < 64*8; s += 128) {
            int r = s >> 3, seg = s & 7;
            int key = kt*64 + r;
            float4 kv = make_float4(0.f,0.f,0.f,0.f), vv = kv;
            if (key < NQ) {
                const float* base = qkv + (size_t)(key*8 + b)*768 + h*32;
                kv = *(const float4*)(base + 256 + seg*4);
                vv = *(const float4*)(base + 512 + seg*4);
            }
            *(float4*)(Ks + r*ATT_LQ + seg*4) = kv;
            *(float4*)(Vs + r*ATT_LQ + seg*4) = vv;
        }
        __syncthreads();

        // ---- S = Q @ K^T (128 x 64) ----
        float acc[2][8][4];
#pragma unroll
        for (int mi = 0; mi < 2; mi++)
#pragma unroll
            for (int j = 0; j < 8; j++)
#pragma unroll
                for (int t = 0; t < 4; t++) acc[mi][j][t] = 0.f;
        const uint32_t* Ku = (const uint32_t*)Ks;
#pragma unroll
        for (int ks = 0; ks < 4; ks++) {
            uint32_t bf[8][2];
            int kb = ks*8 + (lane & 3);
            int nb = lane >> 2;
#pragma unroll
            for (int j = 0; j < 8; j++) {
                bf[j][0] = Ku[(j*8 + nb)*ATT_LQ + kb];
                bf[j][1] = Ku[(j*8 + nb)*ATT_LQ + kb + 4];
            }
#pragma unroll
            for (int mi = 0; mi < 2; mi++)
#pragma unroll
                for (int j = 0; j < 8; j++) MMA_TF32(acc[mi][j], qa[mi][ks], bf[j]);
        }

        // ---- mask invalid keys ----
        int keyb = kt*64 + 2*(lane & 3);
#pragma unroll
        for (int j = 0; j < 8; j++) {
            if (keyb + j*8 >= NQ) {
#pragma unroll
                for (int mi = 0; mi < 2; mi++) {
                    acc[mi][j][0] = -1e30f; acc[mi][j][1] = -1e30f;
                    acc[mi][j][2] = -1e30f; acc[mi][j][3] = -1e30f;
                }
            }
        }

        // ---- online softmax per row instance ----
#pragma unroll
        for (int mi = 0; mi < 2; mi++) {
#pragma unroll
            for (int inst = 0; inst < 2; inst++) {
                int i0 = inst*2;
                float mx = -1e30f;
#pragma unroll
                for (int j = 0; j < 8; j++)
                    mx = fmaxf(mx, fmaxf(acc[mi][j][i0], acc[mi][j][i0+1]));
                mx = fmaxf(mx, __shfl_xor_sync(0xffffffff, mx, 1));
                mx = fmaxf(mx, __shfl_xor_sync(0xffffffff, mx, 2));
                float mo = mrow[mi][inst];
                float mn = fmaxf(mo, mx);
                float c = __expf(mo - mn);
                float sum = 0.f;
#pragma unroll
                for (int j = 0; j < 8; j++) {
                    float p0 = __expf(acc[mi][j][i0]   - mn);
                    float p1 = __expf(acc[mi][j][i0+1] - mn);
                    acc[mi][j][i0] = p0; acc[mi][j][i0+1] = p1;
                    sum += p0 + p1;
                }
                sum += __shfl_xor_sync(0xffffffff, sum, 1);
                sum += __shfl_xor_sync(0xffffffff, sum, 2);
                lrow[mi][inst] = lrow[mi][inst] * c + sum;
                mrow[mi][inst] = mn;
#pragma unroll
                for (int j2 = 0; j2 < 4; j2++) {
                    oacc[mi][j2][i0]   *= c;
                    oacc[mi][j2][i0+1] *= c;
                }
            }
        }

        // ---- store P to smem (own warp rows only) ----
        int pr = lane >> 2, pc = 2*(lane & 3);
#pragma unroll
        for (int mi = 0; mi < 2; mi++)
#pragma unroll
            for (int j = 0; j < 8; j++) {
                *(float2*)(Ps + (warpM + mi*16 + pr)*ATT_LP + j*8 + pc)
                    = make_float2(acc[mi][j][0], acc[mi][j][1]);
                *(float2*)(Ps + (warpM + mi*16 + pr + 8)*ATT_LP + j*8 + pc)
                    = make_float2(acc[mi][j][2], acc[mi][j][3]);
            }
        __syncwarp();

        // ---- O += P @ V ----
        const uint32_t* Vu = (const uint32_t*)Vs;
#pragma unroll
        for (int ks2 = 0; ks2 < 8; ks2++) {
            uint32_t bv[4][2];
            int kb2 = ks2*8 + (lane & 3);
            int nb2 = lane >> 2;
#pragma unroll
            for (int j2 = 0; j2 < 4; j2++) {
                bv[j2][0] = Vu[kb2*ATT_LQ + j2*8 + nb2];
                bv[j2][1] = Vu[(kb2+4)*ATT_LQ + j2*8 + nb2];
            }
#pragma unroll
            for (int mi = 0; mi < 2; mi++) {
                uint32_t pa[4];
                uint32_t addr = smem_u32(Ps + (warpM + mi*16 + frow)*ATT_LP + ks2*8 + fcol);
                LDMX4(pa[0], pa[1], pa[2], pa[3], addr);
#pragma unroll
                for (int j2 = 0; j2 < 4; j2++) MMA_TF32(oacc[mi][j2], pa, bv[j2]);
            }
        }
    }

    // ---- epilogue: normalize, store ----
#pragma unroll
    for (int mi = 0; mi < 2; mi++)
#pragma unroll
        for (int inst = 0; inst < 2; inst++) {
            float inv = 1.f / lrow[mi][inst];
            int r = qt*128 + warpM + mi*16 + (lane >> 2) + inst*8;
            if (r < NQ) {
                float* op = out + ((size_t)r*8 + b)*DIM + h*32;
                int i0 = inst*2;
#pragma unroll
                for (int j2 = 0; j2 < 4; j2++) {
                    *(float2*)(op + j2*8 + 2*(lane & 3))
                        = make_float2(oacc[mi][j2][i0]*inv, oacc[mi][j2][i0+1]*inv);
                }
            }
        }
}

// =========================== MS deformable sampling ===========================
__global__ void msdeform_kernel(const float* __restrict__ value,
                                const float* __restrict__ off,
                                const float* __restrict__ aw,
                                const float* __restrict__ refp,
                                float* __restrict__ out)
{
    int gwarp = (blockIdx.x * blockDim.x + threadIdx.x) >> 5;
    int lane  = threadIdx.x & 31;
    if (gwarp >= MROWS * NH) return;
    int h   = gwarp & 7;
    int row = gwarp >> 3;     // l*B + b
    int b   = row & 7;

    const int Hs[4] = {100, 50, 25, 13};
    const int Ws[4] = {150, 75, 38, 19};
    const int St[4] = {0, 15000, 18750, 19700};

    const float* awp = aw + (size_t)row * 128 + h * 16;
    float w16[16];
    float mx = -1e30f;
#pragma unroll
    for (int i = 0; i < 16; i++) { w16[i] = awp[i]; mx = fmaxf(mx, w16[i]); }
    float ssum = 0.f;
#pragma unroll
    for (int i = 0; i < 16; i++) { w16[i] = __expf(w16[i] - mx); ssum += w16[i]; }
    float invs = 1.f / ssum;

    const float* offp = off + (size_t)row * DIM + h * 32;
    const float* rp   = refp + (size_t)row * NLVL * 4;

    float acc = 0.f;
#pragma unroll
    for (int lv = 0; lv < NLVL; lv++) {
        float r0 = rp[lv*4+0], r1 = rp[lv*4+1], r2 = rp[lv*4+2], r3 = rp[lv*4+3];
        int Wd = Ws[lv], Hh = Hs[lv], st = St[lv];
#pragma unroll
        for (int p = 0; p < NPT; p++) {
            float ox = offp[lv*8 + p*2 + 0];
            float oy = offp[lv*8 + p*2 + 1];
            float locx = r0 + ox * (1.f / NPT) * r2 * 0.5f;
            float locy = r1 + oy * (1.f / NPT) * r3 * 0.5f;
            float x = locx * Wd - 0.5f;
            float y = locy * Hh - 0.5f;
            float x0 = floorf(x), y0 = floorf(y);
            float wq = w16[lv*4 + p] * invs;
            float samp = 0.f;
#pragma unroll
            for (int dy = 0; dy < 2; dy++) {
#pragma unroll
                for (int dx = 0; dx < 2; dx++) {
                    float xi = x0 + dx, yi = y0 + dy;
                    float wbi = (1.f - fabsf(x - xi)) * (1.f - fabsf(y - yi));
                    if (xi >= 0.f && xi < (float)Wd && yi >= 0.f && yi < (float)Hh) {
                        int xc = (int)xi, yc = (int)yi;
                        samp += wbi * value[((size_t)(st + yc * Wd + xc) * BATCH + b) * DIM + h * 32 + lane];
                    }
                }
            }
            acc += wq * samp;
        }
    }
    out[(size_t)row * DIM + h * 32 + lane] = acc;
}

// =========================== fused add + layernorm ===========================
__global__ void add_ln_kernel(const float* __restrict__ X, const float* __restrict__ Y,
                              const float* __restrict__ g, const float* __restrict__ bta,
                              float* __restrict__ out)
{
    int row = blockIdx.x;
    int d = threadIdx.x;
    float x = X[(size_t)row * DIM + d] + Y[(size_t)row * DIM + d];

    __shared__ float red[DIM];
    red[d] = x;
    __syncthreads();
    for (int s = 128; s > 0; s >>= 1) {
        if (d < s) red[d] += red[d + s];
        __syncthreads();
    }
    float mean = red[0] * (1.f / DIM);
    __syncthreads();
    float dx = x - mean;
    red[d] = dx * dx;
    __syncthreads();
    for (int s = 128; s > 0; s >>= 1) {
        if (d < s) red[d] += red[d + s];
        __syncthreads();
    }
    float var = red[0] * (1.f / DIM);
    float r = rsqrtf(var + 1e-5f);
    out[(size_t)row * DIM + d] = dx * r * g[d] + bta[d];
}

// =========================== launch ===========================
extern "C" void kernel_launch(void* const* d_in, const int* in_sizes, int n_in,
                              void* d_out, int out_size)
{
    const float* tgt   = (const float*)d_in[0];
    const float* pos   = (const float*)d_in[1];
    const float* refp  = (const float*)d_in[2];
    const float* mem   = (const float*)d_in[3];
    const float* in_w  = (const float*)d_in[6];
    const float* in_b  = (const float*)d_in[7];
    const float* sow   = (const float*)d_in[8];
    const float* sob   = (const float*)d_in[9];
    const float* n1g   = (const float*)d_in[10];
    const float* n1b   = (const float*)d_in[11];
    const float* n2g   = (const float*)d_in[12];
    const float* n2b   = (const float*)d_in[13];
    const float* n3g   = (const float*)d_in[14];
    const float* n3b   = (const float*)d_in[15];
    const float* off_w = (const float*)d_in[16];
    const float* off_b = (const float*)d_in[17];
    const float* aw_w  = (const float*)d_in[18];
    const float* aw_b  = (const float*)d_in[19];
    const float* val_w = (const float*)d_in[20];
    const float* val_b = (const float*)d_in[21];
    const float* cow   = (const float*)d_in[22];
    const float* cob   = (const float*)d_in[23];
    const float* l1w   = (const float*)d_in[24];
    const float* l1b   = (const float*)d_in[25];
    const float* l2w   = (const float*)d_in[26];
    const float* l2b   = (const float*)d_in[27];
    float* out = (float*)d_out;

    float *p_q, *p_qkv, *p_ao, *p_b1, *p_t1, *p_qry, *p_val, *p_off, *p_aw, *p_ca, *p_b2, *p_t2, *p_h;
    cudaGetSymbolAddress((void**)&p_q,   g_q);
    cudaGetSymbolAddress((void**)&p_qkv, g_qkv);
    cudaGetSymbolAddress((void**)&p_ao,  g_attn_o);
    cudaGetSymbolAddress((void**)&p_b1,  g_buf1);
    cudaGetSymbolAddress((void**)&p_t1,  g_tgt1);
    cudaGetSymbolAddress((void**)&p_qry, g_query);
    cudaGetSymbolAddress((void**)&p_val, g_value);
    cudaGetSymbolAddress((void**)&p_off, g_off);
    cudaGetSymbolAddress((void**)&p_aw,  g_aw);
    cudaGetSymbolAddress((void**)&p_ca,  g_ca);
    cudaGetSymbolAddress((void**)&p_b2,  g_buf2);
    cudaGetSymbolAddress((void**)&p_t2,  g_tgt2);
    cudaGetSymbolAddress((void**)&p_h,   g_h);

    cudaFuncSetAttribute(mma_gemm, cudaFuncAttributeMaxDynamicSharedMemorySize, GEMM_SMEM);
    cudaFuncSetAttribute(attn_mma_kernel, cudaFuncAttributeMaxDynamicSharedMemorySize, ATT_SMEM);

    // 1. q = tgt + pos
    build_q_kernel<<<(MROWS*DIM + 255)/256, 256>>>(tgt, pos, p_q);
    // 2. qh,kh from q; vh from tgt
    gemm(p_q, in_w,            in_b,       p_qkv, MROWS, 512, DIM, 768, 0,   0);
    gemm(tgt, in_w + 512*DIM,  in_b + 512, p_qkv, MROWS, 256, DIM, 768, 512, 0);
    // 3. self-attention (mma flash)
    {
        dim3 grid(8, 64);
        attn_mma_kernel<<<grid, 128, ATT_SMEM>>>(p_qkv, p_ao);
    }
    // 4. SA out proj + residual LN (norm2)
    gemm(p_ao, sow, sob, p_b1, MROWS, DIM, DIM, DIM, 0, 0);
    add_ln_kernel<<<MROWS, DIM>>>(tgt, p_b1, n2g, n2b, p_t1);
    // 5. cross-attention inputs
    build_q_kernel<<<(MROWS*DIM + 255)/256, 256>>>(p_t1, pos, p_qry);
    gemm(mem,   val_w, val_b, p_val, VROWS, DIM, DIM, DIM, 0, 0);
    gemm(p_qry, off_w, off_b, p_off, MROWS, DIM, DIM, DIM, 0, 0);
    gemm(p_qry, aw_w,  aw_b,  p_aw,  MROWS, 128, DIM, 128, 0, 0);
    // 6. deformable sampling
    {
        int nwarps = MROWS * NH;
        int nblocks = (nwarps * 32 + 255) / 256;
        msdeform_kernel<<<nblocks, 256>>>(p_val, p_off, p_aw, refp, p_ca);
    }
    // 7. CA out proj + residual LN (norm1)
    gemm(p_ca, cow, cob, p_b2, MROWS, DIM, DIM, DIM, 0, 0);
    add_ln_kernel<<<MROWS, DIM>>>(p_t1, p_b2, n1g, n1b, p_t2);
    // 8. FFN + LN (norm3)
    gemm(p_t2, l1w, l1b, p_h,  MROWS, DFF, DIM, DFF, 0, 1);
    gemm(p_h,  l2w, l2b, p_b1, MROWS, DIM, DFF, DIM, 0, 0);
    add_ln_kernel<<<MROWS, DIM>>>(p_t2, p_b1, n3g, n3b, out);
}